// round 2
// baseline (speedup 1.0000x reference)
#include <cuda_runtime.h>
#include <cuda_bf16.h>
#include <cstdint>

// Problem sizes (fixed by the dataset)
#define BATCH  8192
#define IN_F   1024
#define OUT_F  1024
#define NB     11
#define KDIM   (IN_F * 12)      // 12288 : per input feature -> [silu, 11 bases]

// GEMM tiling
#define BM 128
#define BN 128
#define BK 24                   // 2 input features per K-chunk (2 * 12)
#define NITER (KDIM / BK)       // 512
#define THREADS 256
#define SKM 136                 // padded smem row stride (128 + 8): banks = 8*t4 + g, conflict-free
#define ABUF (BK * SKM)         // u32 per buffer
#define SMEM_BYTES (4 * ABUF * 4)   // A(2 buf) + B(2 buf)

// Static scratch (allocation-free rule: __device__ globals)
__device__ uint32_t g_Wc[(size_t)OUT_F * KDIM];   // combined weight, tf32 bits, [o][k]
__device__ float    g_xT[(size_t)IN_F * BATCH];   // x transposed, [i][b], full fp32

__device__ __forceinline__ uint32_t f2tf32(float f) {
    uint32_t u;
    asm("cvt.rna.tf32.f32 %0, %1;" : "=r"(u) : "f"(f));
    return u;
}

// silu + 11 cubic B-spline bases, tf32-rounded
__device__ __forceinline__ void eval_bases(float x, uint32_t out[12]) {
    float s = x / (1.0f + expf(-x));
    out[0] = f2tf32(s);
#pragma unroll
    for (int k = 0; k < NB; k++) {
        float c  = -1.25f + 0.25f * (float)k;
        float u  = fabsf(x - c) * 4.0f;           // / GRID_STEP
        float c2 = 2.0f - u;
        float c1 = 1.0f - u;
        float c23 = c2 * c2 * c2;
        float inner = (c23 - 4.0f * c1 * c1 * c1) * (1.0f / 6.0f);
        float outer = c23 * (1.0f / 6.0f);
        float r = (u < 1.0f) ? inner : ((u < 2.0f) ? outer : 0.0f);
        out[k + 1] = f2tf32(r);
    }
}

// ---------------------------------------------------------------------------
// Prep 1: combined weight Wc[o][i*12+j] = {base_w[o][i], spline_w[o][i][0..10]}
// ---------------------------------------------------------------------------
__global__ void prep_wc_kernel(const float* __restrict__ base_w,
                               const float* __restrict__ spline_w) {
    int o = blockIdx.x;
    for (int i = threadIdx.x; i < IN_F; i += blockDim.x) {
        uint32_t* dst = &g_Wc[(size_t)o * KDIM + (size_t)i * 12];
        dst[0] = f2tf32(base_w[(size_t)o * IN_F + i]);
        const float* sp = &spline_w[((size_t)o * IN_F + i) * NB];
#pragma unroll
        for (int j = 0; j < NB; j++) dst[1 + j] = f2tf32(sp[j]);
    }
}

// ---------------------------------------------------------------------------
// Prep 2: x [b][i] -> xT [i][b]  (coalesced column access in the GEMM)
// ---------------------------------------------------------------------------
__global__ void transpose_x_kernel(const float* __restrict__ x) {
    __shared__ float tile[32][33];
    int i0 = blockIdx.x * 32;
    int b0 = blockIdx.y * 32;
    int tx = threadIdx.x, ty = threadIdx.y;
#pragma unroll
    for (int r = 0; r < 32; r += 8)
        tile[ty + r][tx] = x[(size_t)(b0 + ty + r) * IN_F + i0 + tx];
    __syncthreads();
#pragma unroll
    for (int r = 0; r < 32; r += 8)
        g_xT[(size_t)(i0 + ty + r) * BATCH + b0 + tx] = tile[tx][ty + r];
}

// ---------------------------------------------------------------------------
// Fused KAN GEMM: out[b][o] = clip( sum_k A(x)[b][k] * Wc[o][k] )
// A tile generated in-kernel (silu + bases), TF32 mma.sync, fp32 accum.
// ---------------------------------------------------------------------------
#define MMA_TF32(d, a, b)                                                     \
    asm volatile(                                                             \
        "mma.sync.aligned.m16n8k8.row.col.f32.tf32.tf32.f32 "                 \
        "{%0,%1,%2,%3}, {%4,%5,%6,%7}, {%8,%9}, {%0,%1,%2,%3};\n"             \
        : "+f"((d)[0]), "+f"((d)[1]), "+f"((d)[2]), "+f"((d)[3])              \
        : "r"((a)[0]), "r"((a)[1]), "r"((a)[2]), "r"((a)[3]),                 \
          "r"((b)[0]), "r"((b)[1]))

__global__ void __launch_bounds__(THREADS, 1) kan_gemm_kernel(float* __restrict__ out) {
    extern __shared__ uint32_t sm[];
    uint32_t* As = sm;                 // [2][BK][SKM]
    uint32_t* Bs = sm + 2 * ABUF;      // [2][BK][SKM]
#define AS(bf, k, m) As[(bf) * ABUF + (k) * SKM + (m)]
#define BS(bf, k, n) Bs[(bf) * ABUF + (k) * SKM + (n)]

    const int t   = threadIdx.x;
    const int bn0 = blockIdx.x * BN;
    const int bm0 = blockIdx.y * BM;

    // staging roles (every thread does both A-gen and B-copy)
    const int arow = t & 127;          // batch row within tile
    const int aii  = t >> 7;           // which of the 2 input features this chunk
    const int bo   = t >> 1;           // out column within tile
    const int bkh  = (t & 1) * 12;     // which 12-wide half of the K-chunk

    const float*    xcol = g_xT + (size_t)aii * BATCH + bm0 + arow;
    const uint32_t* wrow = g_Wc + (size_t)(bn0 + bo) * KDIM + bkh;

    // mma roles
    const int lane = t & 31, wid = t >> 5;
    const int g  = lane >> 2, t4 = lane & 3;
    const int wm0 = (wid >> 1) * 32;   // 4 warps down M
    const int wn0 = (wid & 1) * 64;    // 2 warps across N

    float acc[2][8][4];
#pragma unroll
    for (int mt = 0; mt < 2; mt++)
#pragma unroll
        for (int nt = 0; nt < 8; nt++)
#pragma unroll
            for (int q = 0; q < 4; q++) acc[mt][nt][q] = 0.0f;

    // -------- prologue: stage iter 0 into buffer 0 --------
    {
        float xv = xcol[0];
        uint32_t av[12];
        eval_bases(xv, av);
#pragma unroll
        for (int j = 0; j < 12; j++) AS(0, aii * 12 + j, arow) = av[j];
        const uint4* wp = (const uint4*)wrow;
        uint4 w0 = wp[0], w1 = wp[1], w2 = wp[2];
        uint32_t wv[12] = {w0.x, w0.y, w0.z, w0.w, w1.x, w1.y, w1.z, w1.w,
                           w2.x, w2.y, w2.z, w2.w};
#pragma unroll
        for (int j = 0; j < 12; j++) BS(0, bkh + j, bo) = wv[j];
    }
    __syncthreads();

    // -------- main loop --------
    for (int it = 0; it < NITER; ++it) {
        const int cur = it & 1;
        float xv = 0.0f;
        uint4 w0, w1, w2;
        const bool has_next = (it + 1 < NITER);
        if (has_next) {                         // issue gmem loads early
            xv = xcol[(size_t)(2 * (it + 1)) * BATCH];
            const uint4* wp = (const uint4*)(wrow + (size_t)(it + 1) * BK);
            w0 = wp[0]; w1 = wp[1]; w2 = wp[2];
        }

        // tensor work on current buffer
#pragma unroll
        for (int kk = 0; kk < BK; kk += 8) {
            uint32_t af[2][4];
#pragma unroll
            for (int mt = 0; mt < 2; mt++) {
                int mb = wm0 + mt * 16 + g;
                af[mt][0] = AS(cur, kk + t4,     mb);
                af[mt][1] = AS(cur, kk + t4,     mb + 8);
                af[mt][2] = AS(cur, kk + t4 + 4, mb);
                af[mt][3] = AS(cur, kk + t4 + 4, mb + 8);
            }
            uint32_t bf[8][2];
#pragma unroll
            for (int nt = 0; nt < 8; nt++) {
                int nb = wn0 + nt * 8 + g;
                bf[nt][0] = BS(cur, kk + t4,     nb);
                bf[nt][1] = BS(cur, kk + t4 + 4, nb);
            }
#pragma unroll
            for (int mt = 0; mt < 2; mt++)
#pragma unroll
                for (int nt = 0; nt < 8; nt++)
                    MMA_TF32(acc[mt][nt], af[mt], bf[nt]);
        }

        if (has_next) {                         // compute + store next buffer
            const int nxt = cur ^ 1;
            uint32_t av[12];
            eval_bases(xv, av);
#pragma unroll
            for (int j = 0; j < 12; j++) AS(nxt, aii * 12 + j, arow) = av[j];
            uint32_t wv[12] = {w0.x, w0.y, w0.z, w0.w, w1.x, w1.y, w1.z, w1.w,
                               w2.x, w2.y, w2.z, w2.w};
#pragma unroll
            for (int j = 0; j < 12; j++) BS(nxt, bkh + j, bo) = wv[j];
        }
        __syncthreads();
    }

    // -------- epilogue: clip + store --------
#pragma unroll
    for (int mt = 0; mt < 2; mt++) {
#pragma unroll
        for (int nt = 0; nt < 8; nt++) {
            int row = bm0 + wm0 + mt * 16 + g;
            int col = bn0 + wn0 + nt * 8 + t4 * 2;
            float2 v01, v23;
            v01.x = fminf(fmaxf(acc[mt][nt][0], -1.0f), 1.0f);
            v01.y = fminf(fmaxf(acc[mt][nt][1], -1.0f), 1.0f);
            v23.x = fminf(fmaxf(acc[mt][nt][2], -1.0f), 1.0f);
            v23.y = fminf(fmaxf(acc[mt][nt][3], -1.0f), 1.0f);
            *(float2*)&out[(size_t)row * OUT_F + col]       = v01;
            *(float2*)&out[(size_t)(row + 8) * OUT_F + col] = v23;
        }
    }
#undef AS
#undef BS
}

// ---------------------------------------------------------------------------
extern "C" void kernel_launch(void* const* d_in, const int* in_sizes, int n_in,
                              void* d_out, int out_size) {
    (void)in_sizes; (void)n_in; (void)out_size;
    const float* x  = (const float*)d_in[0];
    const float* bw = (const float*)d_in[1];
    const float* sw = (const float*)d_in[2];
    float* out = (float*)d_out;

    cudaFuncSetAttribute(kan_gemm_kernel,
                         cudaFuncAttributeMaxDynamicSharedMemorySize, SMEM_BYTES);

    prep_wc_kernel<<<OUT_F, 256>>>(bw, sw);
    transpose_x_kernel<<<dim3(IN_F / 32, BATCH / 32), dim3(32, 8)>>>(x);
    kan_gemm_kernel<<<dim3(OUT_F / BN, BATCH / BM), THREADS, SMEM_BYTES>>>(out);
}

// round 5
// speedup vs baseline: 1.2268x; 1.2268x over previous
#include <cuda_runtime.h>
#include <cstdint>

// ---------------------------------------------------------------- problem
#define BATCH  8192
#define IN_F   1024
#define OUT_F  1024
#define NB     11
#define KDIM   (IN_F * 12)          // 12288, no padding
#define BK     48                   // 4 features per chunk
#define NITER  (KDIM / BK)          // 256
#define BM     128
#define BN     128
#define THREADS 256

// smem layout (words)
#define SKA    136                  // A stride: [k][m], conflict-free
#define SKB    52                   // B stride: [n][k], conflict-free
#define ABUF   (BK * SKA)           // 6528 words
#define BBUF   (BN * SKB)           // 6656 words
#define SMEM_BYTES ((2 * ABUF + 2 * BBUF) * 4)   // 105472 B -> 2 CTAs/SM

// ---------------------------------------------------------------- scratch
__device__ uint32_t g_Wc[(size_t)OUT_F * KDIM];   // tf32 weights [o][k]
__device__ float    g_xT[(size_t)IN_F * BATCH];   // x transposed [i][b]

// ---------------------------------------------------------------- helpers
__device__ __forceinline__ uint32_t f2tf32(float f) {
    uint32_t u;
    asm("cvt.rna.tf32.f32 %0, %1;" : "=r"(u) : "f"(f));
    return u;
}
__device__ __forceinline__ uint32_t smem_u32(const void* p) {
    uint32_t a;
    asm("{ .reg .u64 t; cvta.to.shared.u64 t, %1; cvt.u32.u64 %0, t; }" : "=r"(a) : "l"(p));
    return a;
}
#define CP_ASYNC16(d, s) asm volatile("cp.async.cg.shared.global [%0], [%1], 16;" :: "r"(d), "l"(s) : "memory")
#define CP_COMMIT()      asm volatile("cp.async.commit_group;" ::: "memory")
#define CP_WAIT0()       asm volatile("cp.async.wait_group 0;" ::: "memory")

#define MMA_TF32(d, a, b)                                                     \
    asm volatile(                                                             \
        "mma.sync.aligned.m16n8k8.row.col.f32.tf32.tf32.f32 "                 \
        "{%0,%1,%2,%3}, {%4,%5,%6,%7}, {%8,%9}, {%0,%1,%2,%3};\n"             \
        : "+f"((d)[0]), "+f"((d)[1]), "+f"((d)[2]), "+f"((d)[3])              \
        : "r"((a)[0]), "r"((a)[1]), "r"((a)[2]), "r"((a)[3]),                 \
          "r"((b)[0]), "r"((b)[1]))

// silu + 11 cubic B-spline bases, tf32 bits
__device__ __forceinline__ void gen12(float x, uint32_t v[12]) {
    float s = x / (1.0f + __expf(-x));
    v[0] = f2tf32(s);
#pragma unroll
    for (int k = 0; k < NB; k++) {
        float c  = -1.25f + 0.25f * (float)k;
        float u  = fabsf(x - c) * 4.0f;
        float c2 = 2.0f - u;
        float c1 = 1.0f - u;
        float c23 = c2 * c2 * c2;
        float inner = (c23 - 4.0f * c1 * c1 * c1) * (1.0f / 6.0f);
        float outer = c23 * (1.0f / 6.0f);
        float r = (u < 1.0f) ? inner : ((u < 2.0f) ? outer : 0.0f);
        v[k + 1] = f2tf32(r);
    }
}

// ---------------------------------------------------------------- prep kernels
__global__ void prep_wc_kernel(const float* __restrict__ bw,
                               const float* __restrict__ sw) {
    int idx = blockIdx.x * blockDim.x + threadIdx.x;     // o*1024 + i
    uint32_t v[12];
    v[0] = f2tf32(bw[idx]);
    const float* sp = sw + (size_t)idx * NB;
#pragma unroll
    for (int j = 0; j < NB; j++) v[1 + j] = f2tf32(sp[j]);
    uint4* dst = (uint4*)(g_Wc + (size_t)idx * 12);
#pragma unroll
    for (int q = 0; q < 3; q++)
        dst[q] = make_uint4(v[q * 4], v[q * 4 + 1], v[q * 4 + 2], v[q * 4 + 3]);
}

__global__ void transpose_x_kernel(const float* __restrict__ x) {
    __shared__ float tile[32][33];
    int i0 = blockIdx.x * 32, b0 = blockIdx.y * 32;
    int tx = threadIdx.x, ty = threadIdx.y;
#pragma unroll
    for (int r = 0; r < 32; r += 8)
        tile[ty + r][tx] = x[(size_t)(b0 + ty + r) * IN_F + i0 + tx];
    __syncthreads();
#pragma unroll
    for (int r = 0; r < 32; r += 8)
        g_xT[(size_t)(i0 + ty + r) * BATCH + b0 + tx] = tile[tx][ty + r];
}

// ---------------------------------------------------------------- main GEMM
__global__ void __launch_bounds__(THREADS, 2) kan_gemm_kernel(float* __restrict__ out) {
    extern __shared__ uint32_t sm[];
    uint32_t* As = sm;                    // [2][BK][SKA]
    uint32_t* Bs = sm + 2 * ABUF;         // [2][BN][SKB]
    const uint32_t bs_base = smem_u32(Bs);   // raw shared addr: used ONLY inside cp.async asm

    const int t   = threadIdx.x;
    const int bn0 = blockIdx.x * BN;
    const int bm0 = blockIdx.y * BM;

    // staging roles
    const int rloc = t & 127;             // A row this thread generates
    const int fh   = t >> 7;              // which pair of features (0: f0,f1  1: f2,f3)
    const int brow = t >> 1;              // B row (out column) for cp.async
    const int bu0  = (t & 1) * 6;         // 16B-chunk offset within B row

    const float*    xbase = g_xT + bm0 + rloc;
    const uint32_t* wrow  = g_Wc + (size_t)(bn0 + brow) * KDIM;

    // mma roles
    const int lane = t & 31, wid = t >> 5;
    const int g  = lane >> 2, t4 = lane & 3;
    const int wm0 = (wid >> 1) * 32;      // 4 warps down M
    const int wn0 = (wid & 1) * 64;       // 2 warps across N

    float acc[2][8][4];
#pragma unroll
    for (int mt = 0; mt < 2; mt++)
#pragma unroll
        for (int nt = 0; nt < 8; nt++)
#pragma unroll
            for (int q = 0; q < 4; q++) acc[mt][nt][q] = 0.0f;

    // ---- B stage: cp.async chunk ic into buffer nb (raw shared addr in asm: OK) ----
    auto stageB = [&](int ic, int nb) {
        uint32_t bdst = bs_base + (nb * BBUF + brow * SKB) * 4 + bu0 * 16;
        const char* src = (const char*)(wrow + (size_t)ic * BK) + bu0 * 16;
#pragma unroll
        for (int c = 0; c < 6; c++)
            CP_ASYNC16(bdst + c * 16, src + c * 16);
        CP_COMMIT();
    };

    // ---- A stage: generate bases for 2 features into buffer nb (C++ pointers -> STS) ----
    auto genA = [&](float xv0, float xv1, int nb) {
        uint32_t v[12];
        uint32_t* aptr = As + nb * ABUF + fh * 24 * SKA + rloc;
        gen12(xv0, v);
#pragma unroll
        for (int j = 0; j < 12; j++) aptr[j * SKA] = v[j];
        gen12(xv1, v);
#pragma unroll
        for (int j = 0; j < 12; j++) aptr[(12 + j) * SKA] = v[j];
    };

    // -------- prologue: stage chunk 0 into buffer 0 --------
    stageB(0, 0);
    {
        float x0 = xbase[(size_t)(fh * 2 + 0) * BATCH];
        float x1 = xbase[(size_t)(fh * 2 + 1) * BATCH];
        genA(x0, x1, 0);
    }
    CP_WAIT0();
    __syncthreads();

    // -------- main loop --------
    for (int it = 0; it < NITER; ++it) {
        const int cur = it & 1, nxt = cur ^ 1;
        const bool hn = (it + 1 < NITER);

        float x0 = 0.0f, x1 = 0.0f;
        if (hn) {
            stageB(it + 1, nxt);          // async, lands during MMA section
            x0 = xbase[(size_t)((it + 1) * 4 + fh * 2 + 0) * BATCH];
            x1 = xbase[(size_t)((it + 1) * 4 + fh * 2 + 1) * BATCH];
        }

        // MMA over current buffer: 6 k-steps of 8
        const uint32_t* Ac = As + cur * ABUF;
        const uint32_t* Bc = Bs + cur * BBUF;
#pragma unroll
        for (int kk = 0; kk < BK; kk += 8) {
            uint32_t af[2][4];
#pragma unroll
            for (int mt = 0; mt < 2; mt++) {
                int mb = wm0 + mt * 16 + g;
                af[mt][0] = Ac[(kk + t4)     * SKA + mb];
                af[mt][1] = Ac[(kk + t4)     * SKA + mb + 8];
                af[mt][2] = Ac[(kk + t4 + 4) * SKA + mb];
                af[mt][3] = Ac[(kk + t4 + 4) * SKA + mb + 8];
            }
            uint32_t bf[8][2];
#pragma unroll
            for (int nt = 0; nt < 8; nt++) {
                int nb = wn0 + nt * 8 + g;
                bf[nt][0] = Bc[nb * SKB + kk + t4];
                bf[nt][1] = Bc[nb * SKB + kk + t4 + 4];
            }
#pragma unroll
            for (int mt = 0; mt < 2; mt++)
#pragma unroll
                for (int nt = 0; nt < 8; nt++)
                    MMA_TF32(acc[mt][nt], af[mt], bf[nt]);
        }

        if (hn) genA(x0, x1, nxt);        // A for next chunk (buffer free since it-1)

        CP_WAIT0();
        __syncthreads();
    }

    // -------- epilogue: clip + store --------
#pragma unroll
    for (int mt = 0; mt < 2; mt++) {
#pragma unroll
        for (int nt = 0; nt < 8; nt++) {
            int row = bm0 + wm0 + mt * 16 + g;
            int col = bn0 + wn0 + nt * 8 + t4 * 2;
            float2 v01, v23;
            v01.x = fminf(fmaxf(acc[mt][nt][0], -1.0f), 1.0f);
            v01.y = fminf(fmaxf(acc[mt][nt][1], -1.0f), 1.0f);
            v23.x = fminf(fmaxf(acc[mt][nt][2], -1.0f), 1.0f);
            v23.y = fminf(fmaxf(acc[mt][nt][3], -1.0f), 1.0f);
            *(float2*)&out[(size_t)row * OUT_F + col]       = v01;
            *(float2*)&out[(size_t)(row + 8) * OUT_F + col] = v23;
        }
    }
}

// ---------------------------------------------------------------- launch
extern "C" void kernel_launch(void* const* d_in, const int* in_sizes, int n_in,
                              void* d_out, int out_size) {
    (void)in_sizes; (void)n_in; (void)out_size;
    const float* x  = (const float*)d_in[0];
    const float* bw = (const float*)d_in[1];
    const float* sw = (const float*)d_in[2];
    float* out = (float*)d_out;

    cudaFuncSetAttribute(kan_gemm_kernel,
                         cudaFuncAttributeMaxDynamicSharedMemorySize, SMEM_BYTES);

    prep_wc_kernel<<<(OUT_F * IN_F) / 256, 256>>>(bw, sw);
    transpose_x_kernel<<<dim3(IN_F / 32, BATCH / 32), dim3(32, 8)>>>(x);
    kan_gemm_kernel<<<dim3(OUT_F / BN, BATCH / BM), THREADS, SMEM_BYTES>>>(out);
}